// round 9
// baseline (speedup 1.0000x reference)
#include <cuda_runtime.h>
#include <cuda_fp16.h>
#include <mma.h>
#include <math_constants.h>
#include <cstdint>

using namespace nvcuda;

#define NROWS 131072
#define D     128
#define NC    512
#define R_TILE 64             // rows per CTA
#define THREADS 256

#define MARGIN 1e-3f          // tier-1 top-2 gap threshold (~8 sigma of f16-GEMM ab err)

#define AS_LD 136             // halves per row (mult of 8)
#define CB_LD 132             // floats per row (mult of 4)
// dyn smem: As 64 rows + Bs 128 rows (f16) + Cbuf 64 rows (f32)
#define AS_BYTES (R_TILE * AS_LD * 2)        // 17408
#define BS_BYTES (128 * AS_LD * 2)           // 34816
#define CB_BYTES (R_TILE * CB_LD * 4)        // 33792
#define DYN_BYTES (AS_BYTES + BS_BYTES + CB_BYTES)   // 86016

// ---------------- global scratch (static; no allocation) ----------------
__device__ __half g_cf16[NC * D];                  // codebook f16
__device__ __half g_xnh [(size_t)NROWS * D];       // normalized x, f16
__device__ float  g_xn  [(size_t)NROWS * D];       // normalized x, f32 (tier-2)
__device__ __half g_eu  [(size_t)NROWS * NC];      // unnormalized exp (per-chunk max)

// ================= K0: codebook -> f16 =================
__global__ void k0_prep(const float* __restrict__ cb) {
    int i = blockIdx.x * 256 + threadIdx.x;
    if (i < NC * D) g_cf16[i] = __float2half_rn(cb[i]);
}

// ================= K1: normalize x (R3-verified recipe) =================
__global__ void __launch_bounds__(256)
k1_norm(const float* __restrict__ x, const float* __restrict__ mask) {
    int w = threadIdx.x >> 5, lane = threadIdx.x & 31;
    size_t row = (size_t)blockIdx.x * 8 + w;
    float nud = (1.0f - mask[row]) * 1e-6f;
    float4 v = *reinterpret_cast<const float4*>(x + row * D + lane * 4);
    v.x += nud; v.y += nud; v.z += nud; v.w += nud;
    double sq = (double)v.x * v.x + (double)v.y * v.y + (double)v.z * v.z + (double)v.w * v.w;
    #pragma unroll
    for (int d = 1; d <= 16; d <<= 1) sq += __shfl_xor_sync(0xFFFFFFFFu, sq, d);
    float nf = fmaxf((float)sqrt(sq), 1e-6f);
    float4 o;
    o.x = v.x / nf; o.y = v.y / nf; o.z = v.z / nf; o.w = v.w / nf;  // IEEE fp32 div
    *reinterpret_cast<float4*>(&g_xn[row * D + lane * 4]) = o;
    __half2 h01 = __floats2half2_rn(o.x, o.y);
    __half2 h23 = __floats2half2_rn(o.z, o.w);
    uint2 st;
    st.x = *reinterpret_cast<uint32_t*>(&h01);
    st.y = *reinterpret_cast<uint32_t*>(&h23);
    *reinterpret_cast<uint2*>(&g_xnh[row * D + lane * 4]) = st;
}

// ================= K2: WMMA GEMM1 + softmax/argmin + WMMA GEMM2 =================
__global__ void __launch_bounds__(THREADS, 2)
k2_main(const float* __restrict__ codebook, const float* __restrict__ noise,
        float* __restrict__ out_q, float* __restrict__ out_e, float* __restrict__ out_i) {
    extern __shared__ char dyn[];
    __half* As   = reinterpret_cast<__half*>(dyn);
    __half* Bs   = reinterpret_cast<__half*>(dyn + AS_BYTES);
    float*  Cbuf = reinterpret_cast<float*>(dyn + AS_BYTES + BS_BYTES);

    __shared__ float s_m1[R_TILE], s_m2[R_TILE];
    __shared__ int   s_i1[R_TILE];
    __shared__ float s_mc[4][R_TILE], s_sc[4][R_TILE], s_ci[4][R_TILE];
    __shared__ int   s_flag[R_TILE];
    __shared__ int   s_cnt;
    __shared__ unsigned long long s_onekey;
    __shared__ float s_xr[128];

    const int t = threadIdx.x, w = t >> 5, lane = t & 31;
    const int row0 = blockIdx.x * R_TILE;
    const int rg = w >> 2, cg = w & 3;    // warp -> 32x32 tile of 64x128 output

    if (t < R_TILE) { s_m1[t] = -CUDART_INF_F; s_m2[t] = -CUDART_INF_F; s_i1[t] = 1 << 30; }
    if (t == 0) s_cnt = 0;

    // stage A = xn f16 [64][AS_LD] (uint2 = 4 halves)
    for (int idx = t; idx < R_TILE * 32; idx += THREADS) {
        int r = idx >> 5, p = idx & 31;
        uint2 v = reinterpret_cast<const uint2*>(g_xnh)[(size_t)(row0 + r) * 32 + p];
        *reinterpret_cast<uint2*>(&As[r * AS_LD + 4 * p]) = v;
    }

    // ---------------- GEMM1 + fused per-chunk softmax pass ----------------
    for (int nt = 0; nt < 4; nt++) {
        __syncthreads();   // Bs/Cbuf free
        for (int idx = t; idx < 128 * 32; idx += THREADS) {
            int r = idx >> 5, p = idx & 31;
            uint2 v = reinterpret_cast<const uint2*>(g_cf16)[(size_t)(nt * 128 + r) * 32 + p];
            *reinterpret_cast<uint2*>(&Bs[r * AS_LD + 4 * p]) = v;
        }
        __syncthreads();

        {
            wmma::fragment<wmma::matrix_a, 16, 16, 16, __half, wmma::row_major> af[2];
            wmma::fragment<wmma::matrix_b, 16, 16, 16, __half, wmma::col_major> bf[2];
            wmma::fragment<wmma::accumulator, 16, 16, 16, float> ac[2][2];
            #pragma unroll
            for (int i = 0; i < 2; i++)
                #pragma unroll
                for (int j = 0; j < 2; j++) wmma::fill_fragment(ac[i][j], 0.0f);
            #pragma unroll
            for (int k0 = 0; k0 < 8; k0++) {
                #pragma unroll
                for (int i = 0; i < 2; i++)
                    wmma::load_matrix_sync(af[i], As + (rg * 32 + i * 16) * AS_LD + k0 * 16, AS_LD);
                #pragma unroll
                for (int j = 0; j < 2; j++)
                    wmma::load_matrix_sync(bf[j], Bs + (cg * 32 + j * 16) * AS_LD + k0 * 16, AS_LD);
                #pragma unroll
                for (int i = 0; i < 2; i++)
                    #pragma unroll
                    for (int j = 0; j < 2; j++)
                        wmma::mma_sync(ac[i][j], af[i], bf[j], ac[i][j]);
            }
            #pragma unroll
            for (int i = 0; i < 2; i++)
                #pragma unroll
                for (int j = 0; j < 2; j++)
                    wmma::store_matrix_sync(Cbuf + (rg * 32 + i * 16) * CB_LD + cg * 32 + j * 16,
                                            ac[i][j], CB_LD, wmma::mem_row_major);
        }
        __syncthreads();

        // fused pass: warp w owns rows 8w..8w+7; lane owns 4 consecutive cols
        for (int rr8 = 0; rr8 < 8; rr8++) {
            int rr = w * 8 + rr8;
            size_t go = (size_t)(row0 + rr) * NC + nt * 128 + 4 * lane;
            float4 abv = *reinterpret_cast<const float4*>(&Cbuf[rr * CB_LD + 4 * lane]);
            float4 nv  = *reinterpret_cast<const float4*>(&noise[go]);
            float ab[4] = {abv.x, abv.y, abv.z, abv.w};
            float v [4] = {2.0f * abv.x + nv.x, 2.0f * abv.y + nv.y,
                           2.0f * abv.z + nv.z, 2.0f * abv.w + nv.w};
            float mc = fmaxf(fmaxf(v[0], v[1]), fmaxf(v[2], v[3]));
            // lane-local top-2 of ab
            float lm1 = -CUDART_INF_F, lm2 = -CUDART_INF_F;
            int li = 1 << 30;
            #pragma unroll
            for (int i = 0; i < 4; i++) {
                int ci = nt * 128 + 4 * lane + i;
                if (ab[i] > lm1) { lm2 = lm1; lm1 = ab[i]; li = ci; }
                else             { lm2 = fmaxf(lm2, ab[i]); }
            }
            // warp butterfly: chunk max + top-2 merge
            #pragma unroll
            for (int d2 = 1; d2 <= 16; d2 <<= 1) {
                mc = fmaxf(mc, __shfl_xor_sync(0xFFFFFFFFu, mc, d2));
                float om1 = __shfl_xor_sync(0xFFFFFFFFu, lm1, d2);
                float om2 = __shfl_xor_sync(0xFFFFFFFFu, lm2, d2);
                int   oi  = __shfl_xor_sync(0xFFFFFFFFu, li,  d2);
                if (om1 > lm1)       { lm2 = fmaxf(lm1, om2); lm1 = om1; li = oi; }
                else if (om1 == lm1) { lm2 = lm1; li = min(li, oi); }
                else                 { lm2 = fmaxf(lm2, om1); }
            }
            // exp with chunk max; packed eu store (4 halves = 8 bytes)
            float e0 = __expf(v[0] - mc), e1 = __expf(v[1] - mc);
            float e2 = __expf(v[2] - mc), e3 = __expf(v[3] - mc);
            __half2 h01 = __floats2half2_rn(e0, e1);
            __half2 h23 = __floats2half2_rn(e2, e3);
            uint2 st;
            st.x = *reinterpret_cast<uint32_t*>(&h01);
            st.y = *reinterpret_cast<uint32_t*>(&h23);
            *reinterpret_cast<uint2*>(&g_eu[go]) = st;
            float sum = (e0 + e1) + (e2 + e3);
            #pragma unroll
            for (int d2 = 1; d2 <= 16; d2 <<= 1)
                sum += __shfl_xor_sync(0xFFFFFFFFu, sum, d2);
            if (lane == 0) {
                float gm1 = s_m1[rr], gm2 = s_m2[rr];
                int gi = s_i1[rr];
                if (lm1 > gm1)       { gm2 = fmaxf(gm1, lm2); gm1 = lm1; gi = li; }
                else if (lm1 == gm1) { gm2 = gm1; gi = min(gi, li); }
                else                 { gm2 = fmaxf(gm2, lm1); }
                s_m1[rr] = gm1; s_m2[rr] = gm2; s_i1[rr] = gi;
                s_mc[nt][rr] = mc;
                s_sc[nt][rr] = sum;
            }
        }
    }
    __syncthreads();

    // ---------------- finalize per row ----------------
    if (t < R_TILE) {
        float mc0 = s_mc[0][t], mc1 = s_mc[1][t], mc2 = s_mc[2][t], mc3 = s_mc[3][t];
        float m = fmaxf(fmaxf(mc0, mc1), fmaxf(mc2, mc3));
        float w0 = __expf(mc0 - m), w1 = __expf(mc1 - m),
              w2 = __expf(mc2 - m), w3 = __expf(mc3 - m);
        float s = s_sc[0][t] * w0 + s_sc[1][t] * w1 + s_sc[2][t] * w2 + s_sc[3][t] * w3;
        float inv = 1.0f / s;
        s_ci[0][t] = w0 * inv; s_ci[1][t] = w1 * inv;
        s_ci[2][t] = w2 * inv; s_ci[3][t] = w3 * inv;
        if (s_m1[t] - s_m2[t] > MARGIN) out_i[row0 + t] = (float)s_i1[t];
        else { int p = atomicAdd(&s_cnt, 1); s_flag[p] = t; }
    }
    __syncthreads();

    // ---------------- tier-2: exact reference argmin for flagged rows ----------------
    {
        int cnt = s_cnt;
        for (int f = 0; f < cnt; f++) {
            int rr = s_flag[f];
            int grr = row0 + rr;
            if (t == 0) s_onekey = ~0ull;
            if (t < 128) s_xr[t] = g_xn[(size_t)grr * D + t];
            __syncthreads();
            #pragma unroll
            for (int h = 0; h < 2; h++) {
                int code = t + h * 256;
                const float* cj = codebook + (size_t)code * D;
                float acc = 0.0f;
                #pragma unroll 8
                for (int k = 0; k < 128; k++)
                    acc = fmaf(s_xr[k], cj[k], acc);    // serial ascending k (matches ref)
                float df = (1.0f - 2.0f * acc) + 1.0f;
                unsigned long long key =
                    ((unsigned long long)__float_as_uint(df) << 32) | (unsigned)code;
                atomicMin(&s_onekey, key);
            }
            __syncthreads();
            if (t == 0) out_i[grr] = (float)(unsigned)(s_onekey & 0xffffffffu);
        }
    }

    // ---------------- GEMM2: quantized = e @ C (accumulate over 4 K-chunks) ----------------
    wmma::fragment<wmma::accumulator, 16, 16, 16, float> ac2[2][2];
    #pragma unroll
    for (int i = 0; i < 2; i++)
        #pragma unroll
        for (int j = 0; j < 2; j++) wmma::fill_fragment(ac2[i][j], 0.0f);

    for (int kc = 0; kc < 4; kc++) {
        __syncthreads();
        // stage A = e chunk (scale eu by chunk correction), also emit out_e (f32)
        for (int idx = t; idx < R_TILE * 32; idx += THREADS) {
            int r = idx >> 5, p = idx & 31;
            uint2 packed = *reinterpret_cast<const uint2*>(
                &g_eu[(size_t)(row0 + r) * NC + kc * 128 + 4 * p]);
            __half2 h0 = *reinterpret_cast<__half2*>(&packed.x);
            __half2 h1 = *reinterpret_cast<__half2*>(&packed.y);
            float ci = s_ci[kc][r];
            float4 e4;
            e4.x = __half2float(h0.x) * ci; e4.y = __half2float(h0.y) * ci;
            e4.z = __half2float(h1.x) * ci; e4.w = __half2float(h1.y) * ci;
            *reinterpret_cast<float4*>(&out_e[(size_t)(row0 + r) * NC + kc * 128 + 4 * p]) = e4;
            __half2 o0 = __floats2half2_rn(e4.x, e4.y);
            __half2 o1 = __floats2half2_rn(e4.z, e4.w);
            uint2 st;
            st.x = *reinterpret_cast<uint32_t*>(&o0);
            st.y = *reinterpret_cast<uint32_t*>(&o1);
            *reinterpret_cast<uint2*>(&As[r * AS_LD + 4 * p]) = st;
        }
        // stage B = codebook chunk [k=code][n=d] row-major
        for (int idx = t; idx < 128 * 32; idx += THREADS) {
            int r = idx >> 5, p = idx & 31;
            uint2 v = reinterpret_cast<const uint2*>(g_cf16)[(size_t)(kc * 128 + r) * 32 + p];
            *reinterpret_cast<uint2*>(&Bs[r * AS_LD + 4 * p]) = v;
        }
        __syncthreads();
        {
            wmma::fragment<wmma::matrix_a, 16, 16, 16, __half, wmma::row_major> af[2];
            wmma::fragment<wmma::matrix_b, 16, 16, 16, __half, wmma::row_major> bf[2];
            #pragma unroll
            for (int k0 = 0; k0 < 8; k0++) {
                #pragma unroll
                for (int i = 0; i < 2; i++)
                    wmma::load_matrix_sync(af[i], As + (rg * 32 + i * 16) * AS_LD + k0 * 16, AS_LD);
                #pragma unroll
                for (int j = 0; j < 2; j++)
                    wmma::load_matrix_sync(bf[j], Bs + (k0 * 16) * AS_LD + cg * 32 + j * 16, AS_LD);
                #pragma unroll
                for (int i = 0; i < 2; i++)
                    #pragma unroll
                    for (int j = 0; j < 2; j++)
                        wmma::mma_sync(ac2[i][j], af[i], bf[j], ac2[i][j]);
            }
        }
    }
    __syncthreads();
    #pragma unroll
    for (int i = 0; i < 2; i++)
        #pragma unroll
        for (int j = 0; j < 2; j++)
            wmma::store_matrix_sync(Cbuf + (rg * 32 + i * 16) * CB_LD + cg * 32 + j * 16,
                                    ac2[i][j], CB_LD, wmma::mem_row_major);
    __syncthreads();
    {
        int r = t >> 2, q = t & 3;
        #pragma unroll
        for (int i = 0; i < 8; i++) {
            int c = q * 32 + i * 4;
            float4 o = *reinterpret_cast<float4*>(&Cbuf[r * CB_LD + c]);
            *reinterpret_cast<float4*>(out_q + (size_t)(row0 + r) * D + c) = o;
        }
    }
}

extern "C" void kernel_launch(void* const* d_in, const int* in_sizes, int n_in,
                              void* d_out, int out_size) {
    const float* x        = (const float*)d_in[0];
    const float* mask     = (const float*)d_in[1];
    const float* codebook = (const float*)d_in[2];
    const float* noise    = (const float*)d_in[3];

    float* out   = (float*)d_out;
    float* out_q = out;
    float* out_e = out + (size_t)NROWS * D;
    float* out_i = out_e + (size_t)NROWS * NC;

    cudaFuncSetAttribute(k2_main, cudaFuncAttributeMaxDynamicSharedMemorySize, DYN_BYTES);

    k0_prep<<<(NC * D + 255) / 256, 256>>>(codebook);
    k1_norm<<<NROWS / 8, 256>>>(x, mask);
    k2_main<<<NROWS / R_TILE, THREADS, DYN_BYTES>>>(codebook, noise, out_q, out_e, out_i);
}

// round 10
// speedup vs baseline: 2.5179x; 2.5179x over previous
#include <cuda_runtime.h>
#include <cuda_fp16.h>
#include <mma.h>
#include <math_constants.h>
#include <cstdint>

using namespace nvcuda;

#define NROWS 131072
#define D     128
#define NC    512
#define R_TILE 128
#define THREADS 512

#define MARGIN      1e-3f
#define CAND_MARGIN 1.3e-3f

#define AS_LD 136             // halves per row
#define CB_LD 132             // floats per row
#define AS_BYTES (R_TILE * AS_LD * 2)     // 34816
#define BS_BYTES (R_TILE * AS_LD * 2)     // 34816
#define CB_BYTES (R_TILE * CB_LD * 4)     // 67584
#define DYN_BYTES (AS_BYTES + BS_BYTES + CB_BYTES)   // 137216

// ---------------- global scratch ----------------
__device__ __half g_cf16[NC * D];                  // codebook f16
__device__ __half g_eu  [(size_t)NROWS * NC];      // unnormalized exp (chunk-local max)
__device__ __half g_ab  [(size_t)NROWS * NC];      // ab f16 (tier-2 candidate filter)

// ================= K0: codebook -> f16 =================
__global__ void k0_prep(const float* __restrict__ cb) {
    int i = blockIdx.x * 256 + threadIdx.x;
    if (i < NC * D) g_cf16[i] = __float2half_rn(cb[i]);
}

// ================= K2: everything =================
__global__ void __launch_bounds__(THREADS)
k2_main(const float* __restrict__ x, const float* __restrict__ mask,
        const float* __restrict__ codebook, const float* __restrict__ noise,
        float* __restrict__ out_q, float* __restrict__ out_e, float* __restrict__ out_i) {
    extern __shared__ char dyn[];
    __half* As   = reinterpret_cast<__half*>(dyn);
    __half* Bs   = reinterpret_cast<__half*>(dyn + AS_BYTES);
    float*  Cbuf = reinterpret_cast<float*>(dyn + AS_BYTES + BS_BYTES);

    __shared__ float s_m1[R_TILE], s_m2[R_TILE];
    __shared__ int   s_i1[R_TILE];
    __shared__ float s_mc[4][R_TILE], s_sc[4][R_TILE], s_ci[4][R_TILE];
    __shared__ int   s_flag[R_TILE];
    __shared__ int   s_cnt;
    __shared__ unsigned long long s_onekey;
    __shared__ float s_xr[128];

    const int t = threadIdx.x, w = t >> 5, lane = t & 31;
    const int row0 = blockIdx.x * R_TILE;
    const int rg = w >> 2, cg = w & 3;     // 16 warps -> 4x4 grid of 32x32 tiles

    if (t < R_TILE) { s_m1[t] = -CUDART_INF_F; s_m2[t] = -CUDART_INF_F; s_i1[t] = 1 << 30; }
    if (t == 0) s_cnt = 0;

    const uint2* CF2 = reinterpret_cast<const uint2*>(g_cf16);

    // ---------------- fused normalize + A staging (R3-verified recipe) ----------------
    {
        int r = t >> 2, q = t & 3;                    // 4 threads per row
        const float* xb = x + (size_t)(row0 + r) * D + q * 32;
        float nud = (1.0f - mask[row0 + r]) * 1e-6f;
        float4 xv[8];
        #pragma unroll
        for (int i = 0; i < 8; i++) {
            xv[i] = *reinterpret_cast<const float4*>(xb + 4 * i);
            xv[i].x += nud; xv[i].y += nud; xv[i].z += nud; xv[i].w += nud;
        }
        double sq = 0.0;
        #pragma unroll
        for (int i = 0; i < 8; i++) {
            sq += (double)xv[i].x * xv[i].x; sq += (double)xv[i].y * xv[i].y;
            sq += (double)xv[i].z * xv[i].z; sq += (double)xv[i].w * xv[i].w;
        }
        sq += __shfl_xor_sync(0xFFFFFFFFu, sq, 1);
        sq += __shfl_xor_sync(0xFFFFFFFFu, sq, 2);
        float nf = fmaxf((float)sqrt(sq), 1e-6f);
        #pragma unroll
        for (int i = 0; i < 8; i++) {
            float a0 = xv[i].x / nf, a1 = xv[i].y / nf;    // IEEE fp32 div
            float a2 = xv[i].z / nf, a3 = xv[i].w / nf;
            __half2 h01 = __floats2half2_rn(a0, a1);
            __half2 h23 = __floats2half2_rn(a2, a3);
            uint2 st;
            st.x = *reinterpret_cast<uint32_t*>(&h01);
            st.y = *reinterpret_cast<uint32_t*>(&h23);
            *reinterpret_cast<uint2*>(&As[r * AS_LD + q * 32 + 4 * i]) = st;
        }
    }

    // ---------------- GEMM1 + fused softmax, 4 chunks of 128 codes ----------------
    uint2 pb[8];
    #pragma unroll
    for (int i = 0; i < 8; i++)
        pb[i] = CF2[(size_t)((w + 16 * i) << 5) + lane];   // chunk 0

    for (int nt = 0; nt < 4; nt++) {
        #pragma unroll
        for (int i = 0; i < 8; i++)
            *reinterpret_cast<uint2*>(&Bs[(w + 16 * i) * AS_LD + 4 * lane]) = pb[i];
        __syncthreads();

        {
            wmma::fragment<wmma::matrix_a, 16, 16, 16, __half, wmma::row_major> af[2];
            wmma::fragment<wmma::matrix_b, 16, 16, 16, __half, wmma::col_major> bf[2];
            wmma::fragment<wmma::accumulator, 16, 16, 16, float> ac[2][2];
            #pragma unroll
            for (int i = 0; i < 2; i++)
                #pragma unroll
                for (int j = 0; j < 2; j++) wmma::fill_fragment(ac[i][j], 0.0f);
            #pragma unroll
            for (int k0 = 0; k0 < 8; k0++) {
                #pragma unroll
                for (int i = 0; i < 2; i++)
                    wmma::load_matrix_sync(af[i], As + (rg * 32 + i * 16) * AS_LD + k0 * 16, AS_LD);
                #pragma unroll
                for (int j = 0; j < 2; j++)
                    wmma::load_matrix_sync(bf[j], Bs + (cg * 32 + j * 16) * AS_LD + k0 * 16, AS_LD);
                #pragma unroll
                for (int i = 0; i < 2; i++)
                    #pragma unroll
                    for (int j = 0; j < 2; j++)
                        wmma::mma_sync(ac[i][j], af[i], bf[j], ac[i][j]);
            }
            #pragma unroll
            for (int i = 0; i < 2; i++)
                #pragma unroll
                for (int j = 0; j < 2; j++)
                    wmma::store_matrix_sync(Cbuf + (rg * 32 + i * 16) * CB_LD + cg * 32 + j * 16,
                                            ac[i][j], CB_LD, wmma::mem_row_major);
        }
        if (nt < 3) {
            #pragma unroll
            for (int i = 0; i < 8; i++)
                pb[i] = CF2[(size_t)(((nt + 1) * 128 + w + 16 * i) << 5) + lane];
        }
        __syncthreads();

        // fused pass: warp w owns rows 8w..8w+7; noise batched (MLP 8)
        float4 nz[8];
        #pragma unroll
        for (int i = 0; i < 8; i++)
            nz[i] = *reinterpret_cast<const float4*>(
                &noise[(size_t)(row0 + w * 8 + i) * NC + nt * 128 + 4 * lane]);

        #pragma unroll
        for (int rr8 = 0; rr8 < 8; rr8++) {
            int rr = w * 8 + rr8;
            size_t go = (size_t)(row0 + rr) * NC + nt * 128 + 4 * lane;
            float4 abv = *reinterpret_cast<const float4*>(&Cbuf[rr * CB_LD + 4 * lane]);
            float ab[4] = {abv.x, abv.y, abv.z, abv.w};
            float v [4] = {2.0f * abv.x + nz[rr8].x, 2.0f * abv.y + nz[rr8].y,
                           2.0f * abv.z + nz[rr8].z, 2.0f * abv.w + nz[rr8].w};
            float mc = fmaxf(fmaxf(v[0], v[1]), fmaxf(v[2], v[3]));
            // lane-local top-2 of ab
            float lm1 = -CUDART_INF_F, lm2 = -CUDART_INF_F;
            int li = 1 << 30;
            #pragma unroll
            for (int i = 0; i < 4; i++) {
                int ci = nt * 128 + 4 * lane + i;
                if (ab[i] > lm1) { lm2 = lm1; lm1 = ab[i]; li = ci; }
                else             { lm2 = fmaxf(lm2, ab[i]); }
            }
            // ab f16 copy for tier-2 candidate filter
            {
                __half2 a01 = __floats2half2_rn(ab[0], ab[1]);
                __half2 a23 = __floats2half2_rn(ab[2], ab[3]);
                uint2 st;
                st.x = *reinterpret_cast<uint32_t*>(&a01);
                st.y = *reinterpret_cast<uint32_t*>(&a23);
                *reinterpret_cast<uint2*>(&g_ab[go]) = st;
            }
            #pragma unroll
            for (int d2 = 1; d2 <= 16; d2 <<= 1) {
                mc = fmaxf(mc, __shfl_xor_sync(0xFFFFFFFFu, mc, d2));
                float om1 = __shfl_xor_sync(0xFFFFFFFFu, lm1, d2);
                float om2 = __shfl_xor_sync(0xFFFFFFFFu, lm2, d2);
                int   oi  = __shfl_xor_sync(0xFFFFFFFFu, li,  d2);
                if (om1 > lm1)       { lm2 = fmaxf(lm1, om2); lm1 = om1; li = oi; }
                else if (om1 == lm1) { lm2 = lm1; li = min(li, oi); }
                else                 { lm2 = fmaxf(lm2, om1); }
            }
            float e0 = __expf(v[0] - mc), e1 = __expf(v[1] - mc);
            float e2 = __expf(v[2] - mc), e3 = __expf(v[3] - mc);
            {
                __half2 h01 = __floats2half2_rn(e0, e1);
                __half2 h23 = __floats2half2_rn(e2, e3);
                uint2 st;
                st.x = *reinterpret_cast<uint32_t*>(&h01);
                st.y = *reinterpret_cast<uint32_t*>(&h23);
                *reinterpret_cast<uint2*>(&g_eu[go]) = st;
            }
            float sum = (e0 + e1) + (e2 + e3);
            #pragma unroll
            for (int d2 = 1; d2 <= 16; d2 <<= 1)
                sum += __shfl_xor_sync(0xFFFFFFFFu, sum, d2);
            if (lane == 0) {
                float gm1 = s_m1[rr], gm2 = s_m2[rr];
                int gi = s_i1[rr];
                if (lm1 > gm1)       { gm2 = fmaxf(gm1, lm2); gm1 = lm1; gi = li; }
                else if (lm1 == gm1) { gm2 = gm1; gi = min(gi, li); }
                else                 { gm2 = fmaxf(gm2, lm1); }
                s_m1[rr] = gm1; s_m2[rr] = gm2; s_i1[rr] = gi;
                s_mc[nt][rr] = mc;
                s_sc[nt][rr] = sum;
            }
        }
    }
    __syncthreads();

    // ---------------- finalize per row ----------------
    if (t < R_TILE) {
        float mc0 = s_mc[0][t], mc1 = s_mc[1][t], mc2 = s_mc[2][t], mc3 = s_mc[3][t];
        float m = fmaxf(fmaxf(mc0, mc1), fmaxf(mc2, mc3));
        float w0 = __expf(mc0 - m), w1 = __expf(mc1 - m),
              w2 = __expf(mc2 - m), w3 = __expf(mc3 - m);
        float s = s_sc[0][t] * w0 + s_sc[1][t] * w1 + s_sc[2][t] * w2 + s_sc[3][t] * w3;
        float inv = 1.0f / s;
        s_ci[0][t] = w0 * inv; s_ci[1][t] = w1 * inv;
        s_ci[2][t] = w2 * inv; s_ci[3][t] = w3 * inv;
        if (s_m1[t] - s_m2[t] > MARGIN) out_i[row0 + t] = (float)s_i1[t];
        else { int p = atomicAdd(&s_cnt, 1); s_flag[p] = t; }
    }
    __syncthreads();

    // ---------------- tier-2: exact reference argmin for flagged rows ----------------
    {
        int cnt = s_cnt;
        for (int f = 0; f < cnt; f++) {
            int rr = s_flag[f];
            int grr = row0 + rr;
            if (t == 0) s_onekey = ~0ull;
            if (w == 0) {
                // recompute f32 xn row (R3-verified recipe)
                float nud = (1.0f - mask[grr]) * 1e-6f;
                float4 xv = *reinterpret_cast<const float4*>(&x[(size_t)grr * D + 4 * lane]);
                xv.x += nud; xv.y += nud; xv.z += nud; xv.w += nud;
                double sq = (double)xv.x * xv.x + (double)xv.y * xv.y +
                            (double)xv.z * xv.z + (double)xv.w * xv.w;
                #pragma unroll
                for (int d2 = 1; d2 <= 16; d2 <<= 1)
                    sq += __shfl_xor_sync(0xFFFFFFFFu, sq, d2);
                float nf = fmaxf((float)sqrt(sq), 1e-6f);
                s_xr[4 * lane + 0] = xv.x / nf;
                s_xr[4 * lane + 1] = xv.y / nf;
                s_xr[4 * lane + 2] = xv.z / nf;
                s_xr[4 * lane + 3] = xv.w / nf;
            }
            __syncthreads();
            float abf = __half2float(g_ab[(size_t)grr * NC + t]);
            if (abf >= s_m1[rr] - CAND_MARGIN) {
                const float* cj = codebook + (size_t)t * D;
                float acc = 0.0f;
                #pragma unroll 8
                for (int k = 0; k < 128; k++)
                    acc = fmaf(s_xr[k], cj[k], acc);     // serial ascending k (matches ref)
                float df = (1.0f - 2.0f * acc) + 1.0f;
                unsigned long long key =
                    ((unsigned long long)__float_as_uint(df) << 32) | (unsigned)t;
                atomicMin(&s_onekey, key);
            }
            __syncthreads();
            if (t == 0) out_i[grr] = (float)(unsigned)(s_onekey & 0xffffffffu);
        }
    }
    __syncthreads();

    // ---------------- GEMM2: quantized = e @ C, 4 K-chunks ----------------
    wmma::fragment<wmma::accumulator, 16, 16, 16, float> ac2[2][2];
    #pragma unroll
    for (int i = 0; i < 2; i++)
        #pragma unroll
        for (int j = 0; j < 2; j++) wmma::fill_fragment(ac2[i][j], 0.0f);

    uint2 pa[8], pb2[8];
    #pragma unroll
    for (int i = 0; i < 8; i++) {
        pa[i]  = *reinterpret_cast<const uint2*>(
                    &g_eu[(size_t)(row0 + w + 16 * i) * NC + 4 * lane]);
        pb2[i] = CF2[(size_t)((w + 16 * i) << 5) + lane];
    }

    for (int kc = 0; kc < 4; kc++) {
        #pragma unroll
        for (int i = 0; i < 8; i++) {
            int r = w + 16 * i;
            __half2 h0 = *reinterpret_cast<__half2*>(&pa[i].x);
            __half2 h1 = *reinterpret_cast<__half2*>(&pa[i].y);
            float ci = s_ci[kc][r];
            float4 e4;
            e4.x = __half2float(h0.x) * ci; e4.y = __half2float(h0.y) * ci;
            e4.z = __half2float(h1.x) * ci; e4.w = __half2float(h1.y) * ci;
            *reinterpret_cast<float4*>(
                &out_e[(size_t)(row0 + r) * NC + kc * 128 + 4 * lane]) = e4;
            __half2 o0 = __floats2half2_rn(e4.x, e4.y);
            __half2 o1 = __floats2half2_rn(e4.z, e4.w);
            uint2 st;
            st.x = *reinterpret_cast<uint32_t*>(&o0);
            st.y = *reinterpret_cast<uint32_t*>(&o1);
            *reinterpret_cast<uint2*>(&As[r * AS_LD + 4 * lane]) = st;
            *reinterpret_cast<uint2*>(&Bs[r * AS_LD + 4 * lane]) = pb2[i];
        }
        __syncthreads();
        {
            wmma::fragment<wmma::matrix_a, 16, 16, 16, __half, wmma::row_major> af[2];
            wmma::fragment<wmma::matrix_b, 16, 16, 16, __half, wmma::row_major> bf[2];
            #pragma unroll
            for (int k0 = 0; k0 < 8; k0++) {
                #pragma unroll
                for (int i = 0; i < 2; i++)
                    wmma::load_matrix_sync(af[i], As + (rg * 32 + i * 16) * AS_LD + k0 * 16, AS_LD);
                #pragma unroll
                for (int j = 0; j < 2; j++)
                    wmma::load_matrix_sync(bf[j], Bs + (k0 * 16) * AS_LD + cg * 32 + j * 16, AS_LD);
                #pragma unroll
                for (int i = 0; i < 2; i++)
                    #pragma unroll
                    for (int j = 0; j < 2; j++)
                        wmma::mma_sync(ac2[i][j], af[i], bf[j], ac2[i][j]);
            }
        }
        if (kc < 3) {
            #pragma unroll
            for (int i = 0; i < 8; i++) {
                pa[i]  = *reinterpret_cast<const uint2*>(
                            &g_eu[(size_t)(row0 + w + 16 * i) * NC + (kc + 1) * 128 + 4 * lane]);
                pb2[i] = CF2[(size_t)(((kc + 1) * 128 + w + 16 * i) << 5) + lane];
            }
        }
        __syncthreads();
    }
    #pragma unroll
    for (int i = 0; i < 2; i++)
        #pragma unroll
        for (int j = 0; j < 2; j++)
            wmma::store_matrix_sync(Cbuf + (rg * 32 + i * 16) * CB_LD + cg * 32 + j * 16,
                                    ac2[i][j], CB_LD, wmma::mem_row_major);
    __syncthreads();
    {
        int r = t >> 2, q = t & 3;
        #pragma unroll
        for (int i = 0; i < 8; i++) {
            int c = q * 32 + i * 4;
            float4 o = *reinterpret_cast<float4*>(&Cbuf[r * CB_LD + c]);
            *reinterpret_cast<float4*>(out_q + (size_t)(row0 + r) * D + c) = o;
        }
    }
}

extern "C" void kernel_launch(void* const* d_in, const int* in_sizes, int n_in,
                              void* d_out, int out_size) {
    const float* x        = (const float*)d_in[0];
    const float* mask     = (const float*)d_in[1];
    const float* codebook = (const float*)d_in[2];
    const float* noise    = (const float*)d_in[3];

    float* out   = (float*)d_out;
    float* out_q = out;
    float* out_e = out + (size_t)NROWS * D;
    float* out_i = out_e + (size_t)NROWS * NC;

    cudaFuncSetAttribute(k2_main, cudaFuncAttributeMaxDynamicSharedMemorySize, DYN_BYTES);

    k0_prep<<<(NC * D + 255) / 256, 256>>>(codebook);
    k2_main<<<NROWS / R_TILE, THREADS, DYN_BYTES>>>(x, mask, codebook, noise,
                                                    out_q, out_e, out_i);
}

// round 11
// speedup vs baseline: 3.2411x; 1.2872x over previous
#include <cuda_runtime.h>
#include <cuda_fp16.h>
#include <mma.h>
#include <math_constants.h>
#include <cstdint>

using namespace nvcuda;

#define NROWS 131072
#define D     128
#define NC    512
#define R_TILE 128
#define THREADS 512

#define MARGIN      1e-3f
#define CAND_MARGIN 1.3e-3f

#define AS_LD 136             // halves per row
#define CB_LD 132             // floats per row
#define AS_BYTES (R_TILE * AS_LD * 2)     // 34816
#define BS_BYTES (R_TILE * AS_LD * 2)     // 34816
#define CB_BYTES (R_TILE * CB_LD * 4)     // 67584
#define DYN_BYTES (AS_BYTES + BS_BYTES + CB_BYTES)   // 137216

// ---------------- global scratch ----------------
__device__ __half g_cf16[NC * D];                  // codebook f16
__device__ __half g_eu  [(size_t)NROWS * NC];      // unnormalized exp (chunk-local max)
__device__ __half g_ab  [(size_t)NROWS * NC];      // ab f16 (tier-2 candidate filter)

// ================= K0: codebook -> f16 =================
__global__ void k0_prep(const float* __restrict__ cb) {
    int i = blockIdx.x * 256 + threadIdx.x;
    if (i < NC * D) g_cf16[i] = __float2half_rn(cb[i]);
}

// ================= K2: everything =================
__global__ void __launch_bounds__(THREADS)
k2_main(const float* __restrict__ x, const float* __restrict__ mask,
        const float* __restrict__ codebook, const float* __restrict__ noise,
        float* __restrict__ out_q, float* __restrict__ out_e, float* __restrict__ out_i) {
    extern __shared__ char dyn[];
    __half* As   = reinterpret_cast<__half*>(dyn);
    __half* Bs   = reinterpret_cast<__half*>(dyn + AS_BYTES);
    float*  Cbuf = reinterpret_cast<float*>(dyn + AS_BYTES + BS_BYTES);

    __shared__ float s_m1[R_TILE], s_m2[R_TILE];
    __shared__ int   s_i1[R_TILE];
    __shared__ float s_mc[4][R_TILE], s_sc[4][R_TILE], s_ci[4][R_TILE];
    __shared__ int   s_flag[R_TILE];
    __shared__ int   s_cnt;
    __shared__ float s_xw[16][132];     // warp-private xn rows for tier-2

    const int t = threadIdx.x, w = t >> 5, lane = t & 31;
    const int row0 = blockIdx.x * R_TILE;
    const int rg = w >> 2, cg = w & 3;     // 16 warps -> 4x4 grid of 32x32 tiles

    if (t < R_TILE) { s_m1[t] = -CUDART_INF_F; s_m2[t] = -CUDART_INF_F; s_i1[t] = 1 << 30; }
    if (t == 0) s_cnt = 0;

    const uint2* CF2 = reinterpret_cast<const uint2*>(g_cf16);

    // ---------------- fused normalize + A staging (R3-verified recipe) ----------------
    {
        int r = t >> 2, q = t & 3;                    // 4 threads per row
        const float* xb = x + (size_t)(row0 + r) * D + q * 32;
        float nud = (1.0f - mask[row0 + r]) * 1e-6f;
        float4 xv[8];
        #pragma unroll
        for (int i = 0; i < 8; i++) {
            xv[i] = *reinterpret_cast<const float4*>(xb + 4 * i);
            xv[i].x += nud; xv[i].y += nud; xv[i].z += nud; xv[i].w += nud;
        }
        double sq = 0.0;
        #pragma unroll
        for (int i = 0; i < 8; i++) {
            sq += (double)xv[i].x * xv[i].x; sq += (double)xv[i].y * xv[i].y;
            sq += (double)xv[i].z * xv[i].z; sq += (double)xv[i].w * xv[i].w;
        }
        sq += __shfl_xor_sync(0xFFFFFFFFu, sq, 1);
        sq += __shfl_xor_sync(0xFFFFFFFFu, sq, 2);
        float nf = fmaxf((float)sqrt(sq), 1e-6f);
        #pragma unroll
        for (int i = 0; i < 8; i++) {
            float a0 = xv[i].x / nf, a1 = xv[i].y / nf;    // IEEE fp32 div
            float a2 = xv[i].z / nf, a3 = xv[i].w / nf;
            __half2 h01 = __floats2half2_rn(a0, a1);
            __half2 h23 = __floats2half2_rn(a2, a3);
            uint2 st;
            st.x = *reinterpret_cast<uint32_t*>(&h01);
            st.y = *reinterpret_cast<uint32_t*>(&h23);
            *reinterpret_cast<uint2*>(&As[r * AS_LD + q * 32 + 4 * i]) = st;
        }
    }

    // ---------------- GEMM1 + fused softmax, 4 chunks of 128 codes ----------------
    uint2 pb[8];
    #pragma unroll
    for (int i = 0; i < 8; i++)
        pb[i] = CF2[(size_t)((w + 16 * i) << 5) + lane];   // chunk 0

    for (int nt = 0; nt < 4; nt++) {
        #pragma unroll
        for (int i = 0; i < 8; i++)
            *reinterpret_cast<uint2*>(&Bs[(w + 16 * i) * AS_LD + 4 * lane]) = pb[i];
        __syncthreads();

        // prefetch next chunk's B NOW so the MMA phase hides the latency
        if (nt < 3) {
            #pragma unroll
            for (int i = 0; i < 8; i++)
                pb[i] = CF2[(size_t)(((nt + 1) * 128 + w + 16 * i) << 5) + lane];
        }

        {
            wmma::fragment<wmma::matrix_a, 16, 16, 16, __half, wmma::row_major> af[2];
            wmma::fragment<wmma::matrix_b, 16, 16, 16, __half, wmma::col_major> bf[2];
            wmma::fragment<wmma::accumulator, 16, 16, 16, float> ac[2][2];
            #pragma unroll
            for (int i = 0; i < 2; i++)
                #pragma unroll
                for (int j = 0; j < 2; j++) wmma::fill_fragment(ac[i][j], 0.0f);
            #pragma unroll
            for (int k0 = 0; k0 < 8; k0++) {
                #pragma unroll
                for (int i = 0; i < 2; i++)
                    wmma::load_matrix_sync(af[i], As + (rg * 32 + i * 16) * AS_LD + k0 * 16, AS_LD);
                #pragma unroll
                for (int j = 0; j < 2; j++)
                    wmma::load_matrix_sync(bf[j], Bs + (cg * 32 + j * 16) * AS_LD + k0 * 16, AS_LD);
                #pragma unroll
                for (int i = 0; i < 2; i++)
                    #pragma unroll
                    for (int j = 0; j < 2; j++)
                        wmma::mma_sync(ac[i][j], af[i], bf[j], ac[i][j]);
            }
            #pragma unroll
            for (int i = 0; i < 2; i++)
                #pragma unroll
                for (int j = 0; j < 2; j++)
                    wmma::store_matrix_sync(Cbuf + (rg * 32 + i * 16) * CB_LD + cg * 32 + j * 16,
                                            ac[i][j], CB_LD, wmma::mem_row_major);
        }
        __syncthreads();

        // fused pass: warp w owns rows 8w..8w+7; noise batched (MLP 8)
        float4 nz[8];
        #pragma unroll
        for (int i = 0; i < 8; i++)
            nz[i] = *reinterpret_cast<const float4*>(
                &noise[(size_t)(row0 + w * 8 + i) * NC + nt * 128 + 4 * lane]);

        #pragma unroll
        for (int rr8 = 0; rr8 < 8; rr8++) {
            int rr = w * 8 + rr8;
            size_t go = (size_t)(row0 + rr) * NC + nt * 128 + 4 * lane;
            float4 abv = *reinterpret_cast<const float4*>(&Cbuf[rr * CB_LD + 4 * lane]);
            float ab[4] = {abv.x, abv.y, abv.z, abv.w};
            float v [4] = {2.0f * abv.x + nz[rr8].x, 2.0f * abv.y + nz[rr8].y,
                           2.0f * abv.z + nz[rr8].z, 2.0f * abv.w + nz[rr8].w};
            float mc = fmaxf(fmaxf(v[0], v[1]), fmaxf(v[2], v[3]));
            float lm1 = -CUDART_INF_F, lm2 = -CUDART_INF_F;
            int li = 1 << 30;
            #pragma unroll
            for (int i = 0; i < 4; i++) {
                int ci = nt * 128 + 4 * lane + i;
                if (ab[i] > lm1) { lm2 = lm1; lm1 = ab[i]; li = ci; }
                else             { lm2 = fmaxf(lm2, ab[i]); }
            }
            {   // ab f16 copy for tier-2 candidate filter
                __half2 a01 = __floats2half2_rn(ab[0], ab[1]);
                __half2 a23 = __floats2half2_rn(ab[2], ab[3]);
                uint2 st;
                st.x = *reinterpret_cast<uint32_t*>(&a01);
                st.y = *reinterpret_cast<uint32_t*>(&a23);
                *reinterpret_cast<uint2*>(&g_ab[go]) = st;
            }
            #pragma unroll
            for (int d2 = 1; d2 <= 16; d2 <<= 1) {
                mc = fmaxf(mc, __shfl_xor_sync(0xFFFFFFFFu, mc, d2));
                float om1 = __shfl_xor_sync(0xFFFFFFFFu, lm1, d2);
                float om2 = __shfl_xor_sync(0xFFFFFFFFu, lm2, d2);
                int   oi  = __shfl_xor_sync(0xFFFFFFFFu, li,  d2);
                if (om1 > lm1)       { lm2 = fmaxf(lm1, om2); lm1 = om1; li = oi; }
                else if (om1 == lm1) { lm2 = lm1; li = min(li, oi); }
                else                 { lm2 = fmaxf(lm2, om1); }
            }
            float e0 = __expf(v[0] - mc), e1 = __expf(v[1] - mc);
            float e2 = __expf(v[2] - mc), e3 = __expf(v[3] - mc);
            {
                __half2 h01 = __floats2half2_rn(e0, e1);
                __half2 h23 = __floats2half2_rn(e2, e3);
                uint2 st;
                st.x = *reinterpret_cast<uint32_t*>(&h01);
                st.y = *reinterpret_cast<uint32_t*>(&h23);
                *reinterpret_cast<uint2*>(&g_eu[go]) = st;
            }
            float sum = (e0 + e1) + (e2 + e3);
            #pragma unroll
            for (int d2 = 1; d2 <= 16; d2 <<= 1)
                sum += __shfl_xor_sync(0xFFFFFFFFu, sum, d2);
            if (lane == 0) {
                float gm1 = s_m1[rr], gm2 = s_m2[rr];
                int gi = s_i1[rr];
                if (lm1 > gm1)       { gm2 = fmaxf(gm1, lm2); gm1 = lm1; gi = li; }
                else if (lm1 == gm1) { gm2 = gm1; gi = min(gi, li); }
                else                 { gm2 = fmaxf(gm2, lm1); }
                s_m1[rr] = gm1; s_m2[rr] = gm2; s_i1[rr] = gi;
                s_mc[nt][rr] = mc;
                s_sc[nt][rr] = sum;
            }
        }
    }
    __syncthreads();

    // ---------------- finalize per row ----------------
    if (t < R_TILE) {
        float mc0 = s_mc[0][t], mc1 = s_mc[1][t], mc2 = s_mc[2][t], mc3 = s_mc[3][t];
        float m = fmaxf(fmaxf(mc0, mc1), fmaxf(mc2, mc3));
        float w0 = __expf(mc0 - m), w1 = __expf(mc1 - m),
              w2 = __expf(mc2 - m), w3 = __expf(mc3 - m);
        float s = s_sc[0][t] * w0 + s_sc[1][t] * w1 + s_sc[2][t] * w2 + s_sc[3][t] * w3;
        float inv = 1.0f / s;
        s_ci[0][t] = w0 * inv; s_ci[1][t] = w1 * inv;
        s_ci[2][t] = w2 * inv; s_ci[3][t] = w3 * inv;
        if (s_m1[t] - s_m2[t] > MARGIN) out_i[row0 + t] = (float)s_i1[t];
        else { int p = atomicAdd(&s_cnt, 1); s_flag[p] = t; }
    }
    __syncthreads();

    // ---------------- tier-2: warp-parallel exact reference argmin ----------------
    {
        int cnt = s_cnt;
        for (int f = w; f < cnt; f += 16) {
            int rr = s_flag[f];
            int grr = row0 + rr;
            // warp-private xn row (R3-verified recipe)
            float nud = (1.0f - mask[grr]) * 1e-6f;
            float4 xv = *reinterpret_cast<const float4*>(&x[(size_t)grr * D + 4 * lane]);
            xv.x += nud; xv.y += nud; xv.z += nud; xv.w += nud;
            double sq = (double)xv.x * xv.x + (double)xv.y * xv.y +
                        (double)xv.z * xv.z + (double)xv.w * xv.w;
            #pragma unroll
            for (int d2 = 1; d2 <= 16; d2 <<= 1)
                sq += __shfl_xor_sync(0xFFFFFFFFu, sq, d2);
            float nf = fmaxf((float)sqrt(sq), 1e-6f);
            s_xw[w][4 * lane + 0] = xv.x / nf;
            s_xw[w][4 * lane + 1] = xv.y / nf;
            s_xw[w][4 * lane + 2] = xv.z / nf;
            s_xw[w][4 * lane + 3] = xv.w / nf;
            __syncwarp();
            float m1r = s_m1[rr];
            float bd = CUDART_INF_F;
            int bi = 1 << 30;
            #pragma unroll
            for (int j = 0; j < 16; j++) {
                int code = j * 32 + lane;
                float abf = __half2float(g_ab[(size_t)grr * NC + code]);
                if (abf >= m1r - CAND_MARGIN) {
                    const float* cj = codebook + (size_t)code * D;
                    float acc = 0.0f;
                    #pragma unroll 8
                    for (int k = 0; k < 128; k++)
                        acc = fmaf(s_xw[w][k], cj[k], acc);   // serial ascending k (matches ref)
                    float df = (1.0f - 2.0f * acc) + 1.0f;
                    if (df < bd || (df == bd && code < bi)) { bd = df; bi = code; }
                }
            }
            #pragma unroll
            for (int d2 = 1; d2 <= 16; d2 <<= 1) {
                float od = __shfl_xor_sync(0xFFFFFFFFu, bd, d2);
                int   oi = __shfl_xor_sync(0xFFFFFFFFu, bi, d2);
                if (od < bd || (od == bd && oi < bi)) { bd = od; bi = oi; }
            }
            if (lane == 0) out_i[grr] = (float)bi;
            __syncwarp();
        }
    }
    __syncthreads();

    // ---------------- GEMM2: quantized = e @ C, 4 K-chunks ----------------
    wmma::fragment<wmma::accumulator, 16, 16, 16, float> ac2[2][2];
    #pragma unroll
    for (int i = 0; i < 2; i++)
        #pragma unroll
        for (int j = 0; j < 2; j++) wmma::fill_fragment(ac2[i][j], 0.0f);

    uint2 pa[8], pb2[8];
    #pragma unroll
    for (int i = 0; i < 8; i++) {
        pa[i]  = *reinterpret_cast<const uint2*>(
                    &g_eu[(size_t)(row0 + w + 16 * i) * NC + 4 * lane]);
        pb2[i] = CF2[(size_t)((w + 16 * i) << 5) + lane];
    }

    for (int kc = 0; kc < 4; kc++) {
        #pragma unroll
        for (int i = 0; i < 8; i++) {
            int r = w + 16 * i;
            __half2 h0 = *reinterpret_cast<__half2*>(&pa[i].x);
            __half2 h1 = *reinterpret_cast<__half2*>(&pa[i].y);
            float ci = s_ci[kc][r];
            float4 e4;
            e4.x = __half2float(h0.x) * ci; e4.y = __half2float(h0.y) * ci;
            e4.z = __half2float(h1.x) * ci; e4.w = __half2float(h1.y) * ci;
            *reinterpret_cast<float4*>(
                &out_e[(size_t)(row0 + r) * NC + kc * 128 + 4 * lane]) = e4;
            __half2 o0 = __floats2half2_rn(e4.x, e4.y);
            __half2 o1 = __floats2half2_rn(e4.z, e4.w);
            uint2 st;
            st.x = *reinterpret_cast<uint32_t*>(&o0);
            st.y = *reinterpret_cast<uint32_t*>(&o1);
            *reinterpret_cast<uint2*>(&As[r * AS_LD + 4 * lane]) = st;
            *reinterpret_cast<uint2*>(&Bs[r * AS_LD + 4 * lane]) = pb2[i];
        }
        __syncthreads();
        // prefetch next chunk's A/B NOW; MMA hides the latency
        if (kc < 3) {
            #pragma unroll
            for (int i = 0; i < 8; i++) {
                pa[i]  = *reinterpret_cast<const uint2*>(
                            &g_eu[(size_t)(row0 + w + 16 * i) * NC + (kc + 1) * 128 + 4 * lane]);
                pb2[i] = CF2[(size_t)(((kc + 1) * 128 + w + 16 * i) << 5) + lane];
            }
        }
        {
            wmma::fragment<wmma::matrix_a, 16, 16, 16, __half, wmma::row_major> af[2];
            wmma::fragment<wmma::matrix_b, 16, 16, 16, __half, wmma::row_major> bf[2];
            #pragma unroll
            for (int k0 = 0; k0 < 8; k0++) {
                #pragma unroll
                for (int i = 0; i < 2; i++)
                    wmma::load_matrix_sync(af[i], As + (rg * 32 + i * 16) * AS_LD + k0 * 16, AS_LD);
                #pragma unroll
                for (int j = 0; j < 2; j++)
                    wmma::load_matrix_sync(bf[j], Bs + (k0 * 16) * AS_LD + cg * 32 + j * 16, AS_LD);
                #pragma unroll
                for (int i = 0; i < 2; i++)
                    #pragma unroll
                    for (int j = 0; j < 2; j++)
                        wmma::mma_sync(ac2[i][j], af[i], bf[j], ac2[i][j]);
            }
        }
        __syncthreads();
    }
    #pragma unroll
    for (int i = 0; i < 2; i++)
        #pragma unroll
        for (int j = 0; j < 2; j++)
            wmma::store_matrix_sync(Cbuf + (rg * 32 + i * 16) * CB_LD + cg * 32 + j * 16,
                                    ac2[i][j], CB_LD, wmma::mem_row_major);
    __syncthreads();
    {
        int r = t >> 2, q = t & 3;
        #pragma unroll
        for (int i = 0; i < 8; i++) {
            int c = q * 32 + i * 4;
            float4 o = *reinterpret_cast<float4*>(&Cbuf[r * CB_LD + c]);
            *reinterpret_cast<float4*>(out_q + (size_t)(row0 + r) * D + c) = o;
        }
    }
}

extern "C" void kernel_launch(void* const* d_in, const int* in_sizes, int n_in,
                              void* d_out, int out_size) {
    const float* x        = (const float*)d_in[0];
    const float* mask     = (const float*)d_in[1];
    const float* codebook = (const float*)d_in[2];
    const float* noise    = (const float*)d_in[3];

    float* out   = (float*)d_out;
    float* out_q = out;
    float* out_e = out + (size_t)NROWS * D;
    float* out_i = out_e + (size_t)NROWS * NC;

    cudaFuncSetAttribute(k2_main, cudaFuncAttributeMaxDynamicSharedMemorySize, DYN_BYTES);

    k0_prep<<<(NC * D + 255) / 256, 256>>>(codebook);
    k2_main<<<NROWS / R_TILE, THREADS, DYN_BYTES>>>(x, mask, codebook, noise,
                                                    out_q, out_e, out_i);
}